// round 1
// baseline (speedup 1.0000x reference)
#include <cuda_runtime.h>

static constexpr int DIM   = 8;    // input channels
static constexpr int PATCH = 16;   // patch length
static constexpr int NPAIR = PATCH - 1;   // 15 increment pairs
static constexpr int W     = 2 * DIM;     // lead-lag width = 16

// One block per patch. Thread t = a*16 + b owns:
//   S1[a] (private copy), S2[a,b], S3[a,b,0..15].
// Increments of the lead-lag path are block-sparse: pair k = lead step
// (delta_k in coords [0,8)) then lag step (same delta_k in coords [8,16)).
__global__ __launch_bounds__(256)
void leadlag_sig_kernel(const float* __restrict__ x,
                        float* __restrict__ out,
                        int seq_len)
{
    const int i = blockIdx.x;      // patch index
    const int t = threadIdx.x;     // 0..255
    const int a = t >> 4;          // first signature index (0..15)
    const int b = t & 15;          // second signature index (0..15)

    __shared__ __align__(16) float sdelta[NPAIR][DIM];

    // delta_k[c] = xp[i+k+1][c] - xp[i+k][c], with xp = x padded by 15 zero rows.
    if (t < NPAIR * DIM) {
        int k  = t >> 3;
        int c  = t & 7;
        int g1 = i + k - (PATCH - 2);   // global row of xp[i+k+1]
        int g0 = i + k - (PATCH - 1);   // global row of xp[i+k]
        float v1 = (g1 >= 0) ? x[g1 * DIM + c] : 0.0f;
        float v0 = (g0 >= 0) ? x[g0 * DIM + c] : 0.0f;
        sdelta[k][c] = v1 - v0;
    }
    __syncthreads();

    const bool aL = (a < DIM);
    const bool bL = (b < DIM);
    const int  ai = a & 7;
    const int  bi = b & 7;

    float s1 = 0.0f;       // S1[a]
    float s2 = 0.0f;       // S2[a,b]
    float s3[W];           // S3[a,b,0..15]
    #pragma unroll
    for (int c = 0; c < W; c++) s3[c] = 0.0f;

    #pragma unroll
    for (int k = 0; k < NPAIR; k++) {
        const float4 lo = reinterpret_cast<const float4*>(sdelta[k])[0];
        const float4 hi = reinterpret_cast<const float4*>(sdelta[k])[1];
        const float  da = sdelta[k][ai];
        const float  db = sdelta[k][bi];
        const float  dadb = da * db;

        // ---- lead step: increment lives in coords [0,8) ----
        {
            float coef = s2;
            if (bL)       coef = fmaf(s1 * 0.5f, db, coef);
            if (aL && bL) coef = fmaf(dadb, (1.0f / 6.0f), coef);
            s3[0] = fmaf(coef, lo.x, s3[0]);
            s3[1] = fmaf(coef, lo.y, s3[1]);
            s3[2] = fmaf(coef, lo.z, s3[2]);
            s3[3] = fmaf(coef, lo.w, s3[3]);
            s3[4] = fmaf(coef, hi.x, s3[4]);
            s3[5] = fmaf(coef, hi.y, s3[5]);
            s3[6] = fmaf(coef, hi.z, s3[6]);
            s3[7] = fmaf(coef, hi.w, s3[7]);
            if (bL) {
                s2 = fmaf(s1, db, s2);
                if (aL) s2 = fmaf(dadb, 0.5f, s2);
            }
            if (aL) s1 += da;
        }
        // ---- lag step: increment lives in coords [8,16) ----
        {
            float coef = s2;
            if (!bL)        coef = fmaf(s1 * 0.5f, db, coef);
            if (!aL && !bL) coef = fmaf(dadb, (1.0f / 6.0f), coef);
            s3[8]  = fmaf(coef, lo.x, s3[8]);
            s3[9]  = fmaf(coef, lo.y, s3[9]);
            s3[10] = fmaf(coef, lo.z, s3[10]);
            s3[11] = fmaf(coef, lo.w, s3[11]);
            s3[12] = fmaf(coef, hi.x, s3[12]);
            s3[13] = fmaf(coef, hi.y, s3[13]);
            s3[14] = fmaf(coef, hi.z, s3[14]);
            s3[15] = fmaf(coef, hi.w, s3[15]);
            if (!bL) {
                s2 = fmaf(s1, db, s2);
                if (!aL) s2 = fmaf(dadb, 0.5f, s2);
            }
            if (!aL) s1 += da;
        }
    }

    // ---- write outputs: [L1 | L2 | L3] flattened concatenation ----
    float* out1 = out;
    float* out2 = out + (size_t)seq_len * W;
    float* out3 = out + (size_t)seq_len * (W + W * W);

    if (b == 0) out1[(size_t)i * W + a] = s1;
    out2[(size_t)i * (W * W) + t] = s2;

    float4* o3 = reinterpret_cast<float4*>(out3 + (size_t)i * (W * W * W)
                                                + (size_t)t * W);
    o3[0] = make_float4(s3[0],  s3[1],  s3[2],  s3[3]);
    o3[1] = make_float4(s3[4],  s3[5],  s3[6],  s3[7]);
    o3[2] = make_float4(s3[8],  s3[9],  s3[10], s3[11]);
    o3[3] = make_float4(s3[12], s3[13], s3[14], s3[15]);
}

extern "C" void kernel_launch(void* const* d_in, const int* in_sizes, int n_in,
                              void* d_out, int out_size)
{
    const float* x   = (const float*)d_in[0];
    float*       out = (float*)d_out;
    const int seq_len = in_sizes[0] / DIM;   // 8192
    leadlag_sig_kernel<<<seq_len, 256>>>(x, out, seq_len);
}

// round 2
// speedup vs baseline: 1.0383x; 1.0383x over previous
#include <cuda_runtime.h>

static constexpr int DIM   = 8;          // input channels
static constexpr int PATCH = 16;         // patch length
static constexpr int NPAIR = PATCH - 1;  // 15 increment pairs
static constexpr int W     = 2 * DIM;    // lead-lag width = 16

// ---- packed f32x2 helpers (Blackwell FFMA2 — only reachable via PTX) ----
__device__ __forceinline__ unsigned long long pack2(float lo, float hi) {
    unsigned long long r;
    asm("mov.b64 %0, {%1, %2};" : "=l"(r) : "f"(lo), "f"(hi));
    return r;
}
__device__ __forceinline__ unsigned long long fma2(unsigned long long a,
                                                   unsigned long long b,
                                                   unsigned long long c) {
    unsigned long long d;
    asm("fma.rn.f32x2 %0, %1, %2, %3;" : "=l"(d) : "l"(a), "l"(b), "l"(c));
    return d;
}

// Thread t (128/block): a = t&7, b = t>>3.  b<8 is warp-uniform.
// Each thread owns TWO signature cells: O1=(a,b) and O2=(a+8,b); they share
// da = delta[k][a], db = delta[k][b&7] and all delta vector loads.
// Level-3 rows kept as 8 f32x2 regs per output: v[j]=(s3[2j],s3[2j+1]) j<4
// (lead targets, coords 0..7) and v[4+j]=(s3[8+2j],s3[9+2j]) (lag targets),
// both multiplied by the same packed delta pair d[j].
template <bool BL>
__device__ __forceinline__ void mainloop(
    const float (*__restrict__ sd)[DIM],
    const unsigned long long (*__restrict__ sd2)[4],
    int a, int bi,
    float& s1a, float& s2a, float& s1c, float& s2c,
    unsigned long long* __restrict__ v1,
    unsigned long long* __restrict__ v2)
{
    #pragma unroll
    for (int k = 0; k < NPAIR; k++) {
        const unsigned long long d0 = sd2[k][0];
        const unsigned long long d1 = sd2[k][1];
        const unsigned long long d2 = sd2[k][2];
        const unsigned long long d3 = sd2[k][3];
        const float da = sd[k][a];
        const float db = sd[k][bi];

        float coefL1, coefG1, coefL2, coefG2;
        if (BL) {
            // b < 8: b-channel active in LEAD step, inactive in LAG step.
            // O1 (a<8): lead full, lag trivial.
            float t = da * db;
            float p = s1a * db;
            coefL1 = fmaf(0.5f, p, s2a);
            coefL1 = fmaf(1.0f / 6.0f, t, coefL1);
            s2a    = s2a + p;
            s2a    = fmaf(0.5f, t, s2a);
            s1a   += da;
            coefG1 = s2a;
            // O2 (a>=8): a inactive in lead, active in lag.
            float p2 = s1c * db;
            coefL2 = fmaf(0.5f, p2, s2c);
            s2c   += p2;
            coefG2 = s2c;
            s1c   += da;
        } else {
            // b >= 8: b-channel active in LAG step only.
            // O1 (a<8): lead only updates s1; lag has s1 term.
            coefL1 = s2a;
            s1a   += da;
            float p = s1a * db;
            coefG1 = fmaf(0.5f, p, s2a);
            s2a   += p;
            // O2 (a>=8): lead trivial, lag full.
            coefL2  = s2c;
            float t  = da * db;
            float p2 = s1c * db;
            coefG2 = fmaf(0.5f, p2, s2c);
            coefG2 = fmaf(1.0f / 6.0f, t, coefG2);
            s2c   += p2;
            s2c    = fmaf(0.5f, t, s2c);
            s1c   += da;
        }

        const unsigned long long cL1 = pack2(coefL1, coefL1);
        const unsigned long long cG1 = pack2(coefG1, coefG1);
        const unsigned long long cL2 = pack2(coefL2, coefL2);
        const unsigned long long cG2 = pack2(coefG2, coefG2);

        v1[0] = fma2(cL1, d0, v1[0]);
        v1[1] = fma2(cL1, d1, v1[1]);
        v1[2] = fma2(cL1, d2, v1[2]);
        v1[3] = fma2(cL1, d3, v1[3]);
        v1[4] = fma2(cG1, d0, v1[4]);
        v1[5] = fma2(cG1, d1, v1[5]);
        v1[6] = fma2(cG1, d2, v1[6]);
        v1[7] = fma2(cG1, d3, v1[7]);

        v2[0] = fma2(cL2, d0, v2[0]);
        v2[1] = fma2(cL2, d1, v2[1]);
        v2[2] = fma2(cL2, d2, v2[2]);
        v2[3] = fma2(cL2, d3, v2[3]);
        v2[4] = fma2(cG2, d0, v2[4]);
        v2[5] = fma2(cG2, d1, v2[5]);
        v2[6] = fma2(cG2, d2, v2[6]);
        v2[7] = fma2(cG2, d3, v2[7]);
    }
}

__global__ __launch_bounds__(128)
void leadlag_sig_kernel(const float* __restrict__ x,
                        float* __restrict__ out,
                        int seq_len)
{
    const int i = blockIdx.x;        // patch index
    const int t = threadIdx.x;       // 0..127
    const int a = t & 7;             // first index (low half; thread also does a+8)
    const int b = t >> 3;            // second index 0..15, warp-uniform half

    __shared__ __align__(16) float sd[NPAIR][DIM];

    // delta_k[c] = xp[i+k+1][c] - xp[i+k][c], xp = x padded with 15 zero rows
    if (t < NPAIR * DIM) {
        int k  = t >> 3;
        int c  = t & 7;
        int g1 = i + k - (PATCH - 2);
        int g0 = i + k - (PATCH - 1);
        float v1 = (g1 >= 0) ? x[g1 * DIM + c] : 0.0f;
        float v0 = (g0 >= 0) ? x[g0 * DIM + c] : 0.0f;
        sd[k][c] = v1 - v0;
    }
    __syncthreads();

    const unsigned long long (*sd2)[4] =
        reinterpret_cast<const unsigned long long (*)[4]>(sd);

    float s1a = 0.0f, s2a = 0.0f;    // O1 = (a, b)
    float s1c = 0.0f, s2c = 0.0f;    // O2 = (a+8, b)
    unsigned long long v1[8], v2[8];
    #pragma unroll
    for (int j = 0; j < 8; j++) { v1[j] = 0ull; v2[j] = 0ull; }

    const int bi = b & 7;
    if (b < 8) mainloop<true >(sd, sd2, a, bi, s1a, s2a, s1c, s2c, v1, v2);
    else       mainloop<false>(sd, sd2, a, bi, s1a, s2a, s1c, s2c, v1, v2);

    // ---- outputs: [L1 | L2 | L3] flattened concatenation ----
    float* out1 = out;
    float* out2 = out + (size_t)seq_len * W;
    float* out3 = out + (size_t)seq_len * (W + W * W);

    if (b == 0) {
        out1[(size_t)i * W + a]     = s1a;
        out1[(size_t)i * W + a + 8] = s1c;
    }
    out2[(size_t)i * (W * W) + a * W + b]       = s2a;
    out2[(size_t)i * (W * W) + (a + 8) * W + b] = s2c;

    ulonglong2* o3a = reinterpret_cast<ulonglong2*>(
        out3 + (size_t)i * (W * W * W) + (size_t)(a * W + b) * W);
    ulonglong2* o3c = reinterpret_cast<ulonglong2*>(
        out3 + (size_t)i * (W * W * W) + (size_t)((a + 8) * W + b) * W);
    o3a[0] = make_ulonglong2(v1[0], v1[1]);
    o3a[1] = make_ulonglong2(v1[2], v1[3]);
    o3a[2] = make_ulonglong2(v1[4], v1[5]);
    o3a[3] = make_ulonglong2(v1[6], v1[7]);
    o3c[0] = make_ulonglong2(v2[0], v2[1]);
    o3c[1] = make_ulonglong2(v2[2], v2[3]);
    o3c[2] = make_ulonglong2(v2[4], v2[5]);
    o3c[3] = make_ulonglong2(v2[6], v2[7]);
}

extern "C" void kernel_launch(void* const* d_in, const int* in_sizes, int n_in,
                              void* d_out, int out_size)
{
    const float* x   = (const float*)d_in[0];
    float*       out = (float*)d_out;
    const int seq_len = in_sizes[0] / DIM;   // 8192
    leadlag_sig_kernel<<<seq_len, 128>>>(x, out, seq_len);
}

// round 3
// speedup vs baseline: 1.3906x; 1.3393x over previous
#include <cuda_runtime.h>

static constexpr int DIM   = 8;
static constexpr int PATCH = 16;
static constexpr int NPAIR = PATCH - 1;
static constexpr int W     = 2 * DIM;

__device__ __forceinline__ unsigned long long pack2(float lo, float hi) {
    unsigned long long r;
    asm("mov.b64 %0, {%1, %2};" : "=l"(r) : "f"(lo), "f"(hi));
    return r;
}
__device__ __forceinline__ unsigned long long fma2(unsigned long long a,
                                                   unsigned long long b,
                                                   unsigned long long c) {
    unsigned long long d;
    asm("fma.rn.f32x2 %0, %1, %2, %3;" : "=l"(d) : "l"(a), "l"(b), "l"(c));
    return d;
}

// Thread t (128/block): a=t&7, b=t>>3 (b<8 warp-uniform). Thread owns cells
// (a,b) and (a+8,b); shares da, db, and packed delta loads between them.
template <bool BL>
__device__ __forceinline__ void mainloop(
    const float (*__restrict__ sd)[DIM],
    const unsigned long long (*__restrict__ sd2)[4],
    int a, int bi,
    float& s1a, float& s2a, float& s1c, float& s2c,
    unsigned long long* __restrict__ v1,
    unsigned long long* __restrict__ v2)
{
    #pragma unroll
    for (int k = 0; k < NPAIR; k++) {
        const unsigned long long d0 = sd2[k][0];
        const unsigned long long d1 = sd2[k][1];
        const unsigned long long d2 = sd2[k][2];
        const unsigned long long d3 = sd2[k][3];
        const float da = sd[k][a];
        const float db = sd[k][bi];

        float coefL1, coefG1, coefL2, coefG2;
        if (BL) {
            // b<8: b active in LEAD step only.
            float t = da * db;
            float p = s1a * db;
            coefL1 = fmaf(0.5f, p, s2a);
            coefL1 = fmaf(1.0f / 6.0f, t, coefL1);
            s2a    = s2a + p;
            s2a    = fmaf(0.5f, t, s2a);
            s1a   += da;
            coefG1 = s2a;
            float p2 = s1c * db;
            coefL2 = fmaf(0.5f, p2, s2c);
            s2c   += p2;
            coefG2 = s2c;
            s1c   += da;
        } else {
            // b>=8: b active in LAG step only.
            coefL1 = s2a;
            s1a   += da;
            float p = s1a * db;
            coefG1 = fmaf(0.5f, p, s2a);
            s2a   += p;
            coefL2  = s2c;
            float t  = da * db;
            float p2 = s1c * db;
            coefG2 = fmaf(0.5f, p2, s2c);
            coefG2 = fmaf(1.0f / 6.0f, t, coefG2);
            s2c   += p2;
            s2c    = fmaf(0.5f, t, s2c);
            s1c   += da;
        }

        const unsigned long long cL1 = pack2(coefL1, coefL1);
        const unsigned long long cG1 = pack2(coefG1, coefG1);
        const unsigned long long cL2 = pack2(coefL2, coefL2);
        const unsigned long long cG2 = pack2(coefG2, coefG2);

        v1[0] = fma2(cL1, d0, v1[0]);  v1[1] = fma2(cL1, d1, v1[1]);
        v1[2] = fma2(cL1, d2, v1[2]);  v1[3] = fma2(cL1, d3, v1[3]);
        v1[4] = fma2(cG1, d0, v1[4]);  v1[5] = fma2(cG1, d1, v1[5]);
        v1[6] = fma2(cG1, d2, v1[6]);  v1[7] = fma2(cG1, d3, v1[7]);

        v2[0] = fma2(cL2, d0, v2[0]);  v2[1] = fma2(cL2, d1, v2[1]);
        v2[2] = fma2(cL2, d2, v2[2]);  v2[3] = fma2(cL2, d3, v2[3]);
        v2[4] = fma2(cG2, d0, v2[4]);  v2[5] = fma2(cG2, d1, v2[5]);
        v2[6] = fma2(cG2, d2, v2[6]);  v2[7] = fma2(cG2, d3, v2[7]);
    }
}

// XOR-swizzled chunk index: 16B chunk c (0..1023), swizzled by its 64-chunk
// group to make both the scattered write phase and the linear read phase
// bank-conflict-free.
__device__ __forceinline__ int swz(int c) {
    return c ^ ((c >> 6) & 7);
}

__global__ __launch_bounds__(128)
void leadlag_sig_kernel(const float* __restrict__ x,
                        float* __restrict__ out,
                        int seq_len)
{
    const int i = blockIdx.x;
    const int t = threadIdx.x;       // 0..127
    const int a = t & 7;
    const int b = t >> 3;            // 0..15, warp-uniform half

    __shared__ __align__(16) float sd[NPAIR][DIM];
    __shared__ __align__(16) ulonglong2 s3buf[1024];   // 16 KB transpose buffer

    if (t < NPAIR * DIM) {
        int k  = t >> 3;
        int c  = t & 7;
        int g1 = i + k - (PATCH - 2);
        int g0 = i + k - (PATCH - 1);
        float v1 = (g1 >= 0) ? x[g1 * DIM + c] : 0.0f;
        float v0 = (g0 >= 0) ? x[g0 * DIM + c] : 0.0f;
        sd[k][c] = v1 - v0;
    }
    __syncthreads();

    const unsigned long long (*sd2)[4] =
        reinterpret_cast<const unsigned long long (*)[4]>(sd);

    float s1a = 0.0f, s2a = 0.0f;
    float s1c = 0.0f, s2c = 0.0f;
    unsigned long long v1[8], v2[8];
    #pragma unroll
    for (int j = 0; j < 8; j++) { v1[j] = 0ull; v2[j] = 0ull; }

    const int bi = b & 7;
    if (b < 8) mainloop<true >(sd, sd2, a, bi, s1a, s2a, s1c, s2c, v1, v2);
    else       mainloop<false>(sd, sd2, a, bi, s1a, s2a, s1c, s2c, v1, v2);

    // ---- stage level-3 rows into swizzled smem ----
    {
        const int rA = a * W + b;            // row of output (a ,b)
        const int rC = (a + 8) * W + b;      // row of output (a+8,b)
        #pragma unroll
        for (int s = 0; s < 4; s++) {
            s3buf[swz(4 * rA + s)] = make_ulonglong2(v1[2 * s], v1[2 * s + 1]);
            s3buf[swz(4 * rC + s)] = make_ulonglong2(v2[2 * s], v2[2 * s + 1]);
        }
    }

    // ---- non-L3 outputs while waiting ----
    float* out1 = out;
    float* out2 = out + (size_t)seq_len * W;
    float* out3 = out + (size_t)seq_len * (W + W * W);

    if (b == 0) {
        out1[(size_t)i * W + a]     = s1a;
        out1[(size_t)i * W + a + 8] = s1c;
    }
    out2[(size_t)i * (W * W) + a * W + b]       = s2a;
    out2[(size_t)i * (W * W) + (a + 8) * W + b] = s2c;

    __syncthreads();

    // ---- coalesced sweep: warp writes lane-contiguous 512B per STG.128 ----
    ulonglong2* o3 = reinterpret_cast<ulonglong2*>(out3 + (size_t)i * (W * W * W));
    #pragma unroll
    for (int j = 0; j < 8; j++) {
        int c = j * 128 + t;
        o3[c] = s3buf[swz(c)];
    }
}

extern "C" void kernel_launch(void* const* d_in, const int* in_sizes, int n_in,
                              void* d_out, int out_size)
{
    const float* x   = (const float*)d_in[0];
    float*       out = (float*)d_out;
    const int seq_len = in_sizes[0] / DIM;   // 8192
    leadlag_sig_kernel<<<seq_len, 128>>>(x, out, seq_len);
}

// round 4
// speedup vs baseline: 1.4426x; 1.0373x over previous
#include <cuda_runtime.h>

static constexpr int DIM   = 8;
static constexpr int PATCH = 16;
static constexpr int NPAIR = PATCH - 1;
static constexpr int W     = 2 * DIM;

__device__ __forceinline__ unsigned long long pack2(float lo, float hi) {
    unsigned long long r;
    asm("mov.b64 %0, {%1, %2};" : "=l"(r) : "f"(lo), "f"(hi));
    return r;
}
__device__ __forceinline__ unsigned long long fma2(unsigned long long a,
                                                   unsigned long long b,
                                                   unsigned long long c) {
    unsigned long long d;
    asm("fma.rn.f32x2 %0, %1, %2, %3;" : "=l"(d) : "l"(a), "l"(b), "l"(c));
    return d;
}

// Thread t (128/block): p = t>>3 (0..15), q = t&7. Thread owns signature
// cells (p,q) and (p,q+8). Both share s1 = S1[p] and the per-pair deltas
// dp = delta[k][p&7], dq = delta[k][q]. p<8 is warp-uniform (template AL).
template <bool AL>
__device__ __forceinline__ void mainloop(
    const float (*__restrict__ sd)[DIM],
    int pl, int q,
    float& s1, float& s2A, float& s2C,
    unsigned long long* __restrict__ vA,
    unsigned long long* __restrict__ vC)
{
    #pragma unroll
    for (int k = 0; k < NPAIR; k++) {
        const ulonglong2* sdv = reinterpret_cast<const ulonglong2*>(sd[k]);
        const ulonglong2 dA = sdv[0];
        const ulonglong2 dB = sdv[1];
        const float dp = sd[k][pl];
        const float dq = sd[k][q];

        float coefAL, coefAG, coefCL, coefCG;
        if (AL) {
            // p<8: p active in LEAD. A.b=q active in LEAD, C.b=q+8 in LAG.
            float tt = dp * dq;
            float pa = s1 * dq;
            coefAL = fmaf(0.5f, pa, s2A);
            coefAL = fmaf(1.0f / 6.0f, tt, coefAL);
            coefCL = s2C;
            s2A    = s2A + pa;
            s2A    = fmaf(0.5f, tt, s2A);
            s1    += dp;
            // lag: p inactive, C.b active (uses updated s1).
            float pc = s1 * dq;
            coefAG = s2A;
            coefCG = fmaf(0.5f, pc, s2C);
            s2C   += pc;
        } else {
            // p>=8: p active in LAG. A.b=q active in LEAD (uses pre-update s1).
            float pa = s1 * dq;
            coefAL = fmaf(0.5f, pa, s2A);
            coefCL = s2C;
            s2A   += pa;
            // lag: p active, C.b active (pc uses pre-update s1).
            coefAG = s2A;
            float tt = dp * dq;
            float pc = s1 * dq;
            coefCG = fmaf(0.5f, pc, s2C);
            coefCG = fmaf(1.0f / 6.0f, tt, coefCG);
            s2C   += pc;
            s2C    = fmaf(0.5f, tt, s2C);
            s1    += dp;
        }

        const unsigned long long cAL = pack2(coefAL, coefAL);
        const unsigned long long cAG = pack2(coefAG, coefAG);
        const unsigned long long cCL = pack2(coefCL, coefCL);
        const unsigned long long cCG = pack2(coefCG, coefCG);

        vA[0] = fma2(cAL, dA.x, vA[0]);  vA[1] = fma2(cAL, dA.y, vA[1]);
        vA[2] = fma2(cAL, dB.x, vA[2]);  vA[3] = fma2(cAL, dB.y, vA[3]);
        vA[4] = fma2(cAG, dA.x, vA[4]);  vA[5] = fma2(cAG, dA.y, vA[5]);
        vA[6] = fma2(cAG, dB.x, vA[6]);  vA[7] = fma2(cAG, dB.y, vA[7]);

        vC[0] = fma2(cCL, dA.x, vC[0]);  vC[1] = fma2(cCL, dA.y, vC[1]);
        vC[2] = fma2(cCL, dB.x, vC[2]);  vC[3] = fma2(cCL, dB.y, vC[3]);
        vC[4] = fma2(cCG, dA.x, vC[4]);  vC[5] = fma2(cCG, dA.y, vC[5]);
        vC[6] = fma2(cCG, dB.x, vC[6]);  vC[7] = fma2(cCG, dB.y, vC[7]);
    }
}

// TMA-SW128-style chunk swizzle: conflict-free for this kernel's write
// pattern (rows 16p+q / 16p+q+8, fixed p per 8-lane phase) AND for the
// linear sweep (consecutive chunks per phase).
__device__ __forceinline__ int swz(int c) {
    return c ^ ((c >> 3) & 7);
}

__global__ __launch_bounds__(128, 8)
void leadlag_sig_kernel(const float* __restrict__ x,
                        float* __restrict__ out,
                        int seq_len)
{
    const int i = blockIdx.x;
    const int t = threadIdx.x;       // 0..127
    const int p = t >> 3;            // first index 0..15 (warp-uniform half)
    const int q = t & 7;             // second index low part

    __shared__ __align__(16) float sd[NPAIR][DIM];
    __shared__ __align__(16) ulonglong2 s3buf[1024];   // 16 KB transpose buffer

    if (t < NPAIR * DIM) {
        int k  = t >> 3;
        int c  = t & 7;
        int g1 = i + k - (PATCH - 2);
        int g0 = i + k - (PATCH - 1);
        float v1 = (g1 >= 0) ? x[g1 * DIM + c] : 0.0f;
        float v0 = (g0 >= 0) ? x[g0 * DIM + c] : 0.0f;
        sd[k][c] = v1 - v0;
    }
    __syncthreads();

    float s1 = 0.0f, s2A = 0.0f, s2C = 0.0f;
    unsigned long long vA[8], vC[8];
    #pragma unroll
    for (int j = 0; j < 8; j++) { vA[j] = 0ull; vC[j] = 0ull; }

    const int pl = p & 7;
    if (p < 8) mainloop<true >(sd, pl, q, s1, s2A, s2C, vA, vC);
    else       mainloop<false>(sd, pl, q, s1, s2A, s2C, vA, vC);

    // ---- stage level-3 rows into swizzled smem ----
    {
        const int rA = p * W + q;        // row of cell (p, q)
        const int rC = rA + 8;           // row of cell (p, q+8)
        #pragma unroll
        for (int s = 0; s < 4; s++) {
            s3buf[swz(4 * rA + s)] = make_ulonglong2(vA[2 * s], vA[2 * s + 1]);
            s3buf[swz(4 * rC + s)] = make_ulonglong2(vC[2 * s], vC[2 * s + 1]);
        }
    }

    // ---- level-1 / level-2 outputs ----
    float* out1 = out;
    float* out2 = out + (size_t)seq_len * W;
    float* out3 = out + (size_t)seq_len * (W + W * W);

    if (q == 0) out1[(size_t)i * W + p] = s1;
    out2[(size_t)i * (W * W) + p * W + q]     = s2A;
    out2[(size_t)i * (W * W) + p * W + q + 8] = s2C;

    __syncthreads();

    // ---- coalesced sweep: lane-contiguous 512B per warp STG.128 ----
    ulonglong2* o3 = reinterpret_cast<ulonglong2*>(out3 + (size_t)i * (W * W * W));
    #pragma unroll
    for (int j = 0; j < 8; j++) {
        int c = j * 128 + t;
        o3[c] = s3buf[swz(c)];
    }
}

extern "C" void kernel_launch(void* const* d_in, const int* in_sizes, int n_in,
                              void* d_out, int out_size)
{
    const float* x   = (const float*)d_in[0];
    float*       out = (float*)d_out;
    const int seq_len = in_sizes[0] / DIM;   // 8192
    leadlag_sig_kernel<<<seq_len, 128>>>(x, out, seq_len);
}